// round 2
// baseline (speedup 1.0000x reference)
#include <cuda_runtime.h>
#include <math.h>

// Problem constants
#define BMAX 4096
#define Mc   64
#define Dc   512
#define DOUTc 256
#define NHc  8

// ---------------- scratch (device globals; no allocations) ----------------
__device__ __align__(16) float g_qvec[Dc];
__device__ __align__(16) float g_qk[NHc * Dc];          // 8 x 512
__device__ __align__(16) float g_cbias[Dc];             // opb + Wo . bv
__device__ __align__(16) float g_Uattn[(size_t)BMAX * NHc * Dc]; // 64 MB
__device__ __align__(16) float g_CTX[(size_t)BMAX * Dc];
__device__ __align__(16) float g_Z[(size_t)BMAX * Dc];  // U0 then z
__device__ __align__(16) float g_Zn[(size_t)BMAX * Dc];
__device__ __align__(16) float g_T[(size_t)BMAX * Dc];

__device__ __forceinline__ float warp_sum(float v) {
#pragma unroll
    for (int o = 16; o; o >>= 1) v += __shfl_xor_sync(0xffffffffu, v, o);
    return v;
}
__device__ __forceinline__ float warp_max(float v) {
#pragma unroll
    for (int o = 16; o; o >>= 1) v = fmaxf(v, __shfl_xor_sync(0xffffffffu, v, o));
    return v;
}

// ---------------- setup 1: qvec = Wq.agg + bq ; cbias = opb + Wo.bv -------
__global__ void k_setup1(const float* __restrict__ agg,
                         const float* __restrict__ ipw,
                         const float* __restrict__ ipb,
                         const float* __restrict__ opw,
                         const float* __restrict__ opb) {
    __shared__ float red[4];
    const int d = blockIdx.x;            // 0..1023
    const int t = threadIdx.x;           // 128 threads
    const int lane = t & 31, wid = t >> 5;
    const bool isq = d < Dc;
    const float* row = isq ? (ipw + (size_t)d * Dc)
                           : (opw + (size_t)(d - Dc) * Dc);
    const float* vec = isq ? agg : (ipb + 2 * Dc);  // agg or bv
    float acc = 0.f;
    for (int e = t; e < Dc; e += 128) acc += row[e] * vec[e];
    acc = warp_sum(acc);
    if (lane == 0) red[wid] = acc;
    __syncthreads();
    if (t == 0) {
        float s = red[0] + red[1] + red[2] + red[3];
        if (isq) g_qvec[d] = s + ipb[d];
        else     g_cbias[d - Dc] = s + opb[d - Dc];
    }
}

// ---------------- setup 2: qk[h,e] = sum_hd qvec[h*64+hd] * Wk[h*64+hd,e] -
__global__ void k_setup2(const float* __restrict__ ipw) {
    const int idx = blockIdx.x * 256 + threadIdx.x;  // 0..4095
    const int h = idx >> 9, e = idx & 511;
    const float* base = ipw + (size_t)(Dc + h * 64) * Dc + e;  // Wk rows
    float acc = 0.f;
#pragma unroll 16
    for (int hd = 0; hd < 64; ++hd)
        acc += g_qvec[h * 64 + hd] * base[(size_t)hd * Dc];
    g_qk[idx] = acc;
}

// ---------------- attention per batch row ---------------------------------
// scores -> softmax -> 9 weighted sums over m of H[b]  (U0 + 8 head contexts)
__global__ __launch_bounds__(256) void k_attn(const float* __restrict__ H,
                                              const float* __restrict__ w) {
    __shared__ float s_qk[NHc * Dc];     // 16 KB
    __shared__ float s_at[NHc][Mc];      // scores then attn
    __shared__ float s_w[Mc];
    const int b = blockIdx.x;
    const int t = threadIdx.x;
    const int lane = t & 31, wid = t >> 5;
    const float* Hb = H + (size_t)b * Mc * Dc;

    for (int i = t; i < NHc * Dc; i += 256) s_qk[i] = g_qk[i];
    if (t < Mc) s_w[t] = w[b * Mc + t];
    __syncthreads();

    // ---- scores: warp `wid` handles m = wid*8 .. wid*8+7
#pragma unroll 1
    for (int mi = 0; mi < 8; ++mi) {
        const int m = (wid << 3) + mi;
        const float* hr = Hb + m * Dc;
        float a[NHc];
#pragma unroll
        for (int h = 0; h < NHc; ++h) a[h] = 0.f;
#pragma unroll
        for (int i = 0; i < 16; ++i) {
            const int d = lane + (i << 5);
            const float hv = hr[d];
#pragma unroll
            for (int h = 0; h < NHc; ++h) a[h] = fmaf(s_qk[h * Dc + d], hv, a[h]);
        }
#pragma unroll
        for (int h = 0; h < NHc; ++h) {
            float v = warp_sum(a[h]);
            if (lane == 0) s_at[h][m] = v * 0.125f;  // 1/sqrt(64)
        }
    }
    __syncthreads();

    // ---- softmax: warp `wid` handles head wid
    {
        const int h = wid;
        float v0 = s_at[h][lane], v1 = s_at[h][lane + 32];
        float mx = warp_max(fmaxf(v0, v1));
        float e0 = __expf(v0 - mx), e1 = __expf(v1 - mx);
        float s = warp_sum(e0 + e1);
        float inv = 1.0f / s;
        s_at[h][lane] = e0 * inv;
        s_at[h][lane + 32] = e1 * inv;
    }
    __syncthreads();

    // ---- 9 weighted sums: thread handles columns d0=t, d1=t+256
    const int d0 = t, d1 = t + 256;
    float u0a = 0.f, u0b = 0.f;
    float ua[NHc], ub[NHc];
#pragma unroll
    for (int h = 0; h < NHc; ++h) { ua[h] = 0.f; ub[h] = 0.f; }
#pragma unroll 4
    for (int m = 0; m < Mc; ++m) {
        const float wm = s_w[m];
        const float h0 = Hb[m * Dc + d0];
        const float h1 = Hb[m * Dc + d1];
        u0a = fmaf(wm, h0, u0a);
        u0b = fmaf(wm, h1, u0b);
#pragma unroll
        for (int h = 0; h < NHc; ++h) {
            const float a = s_at[h][m];
            ua[h] = fmaf(a, h0, ua[h]);
            ub[h] = fmaf(a, h1, ub[h]);
        }
    }
    g_Z[(size_t)b * Dc + d0] = u0a;
    g_Z[(size_t)b * Dc + d1] = u0b;
#pragma unroll
    for (int h = 0; h < NHc; ++h) {
        const size_t base = ((size_t)b * NHc + h) * Dc;
        g_Uattn[base + d0] = ua[h];
        g_Uattn[base + d1] = ub[h];
    }
}

// ---------------- generic 64x64x16 tiled fp32 GEMM, C = A @ Bw^T + epi ----
// MODE 0: CTX[b, h*64+j] = sum_e Uattn[b,h,e] * Wv[h*64+j, e]       (jb=head)
// MODE 1: Z = U0 + CTX @ Wo^T + cbias
// MODE 2: T = gelu(Zn @ W1^T + b1)
// MODE 3: OUT = T @ W2^T + b2   (N = 256), nan_to_num
template <int MODE>
__global__ __launch_bounds__(256) void k_gemm(const float* __restrict__ Bw,
                                              const float* __restrict__ bias,
                                              float* __restrict__ outp) {
    const int bb = blockIdx.x, jb = blockIdx.y;
    const int t = threadIdx.x;
    const int tx = t & 15, ty = t >> 4;
    __shared__ float As[16][68];
    __shared__ float Bs[16][68];

    const float* A = (MODE == 0) ? g_Uattn
                   : (MODE == 1) ? g_CTX
                   : (MODE == 2) ? g_Zn
                                 : g_T;

    float acc[4][4];
#pragma unroll
    for (int i = 0; i < 4; ++i)
#pragma unroll
        for (int j = 0; j < 4; ++j) acc[i][j] = 0.f;

    const int r  = t >> 2;           // 0..63
    const int c4 = (t & 3) << 2;     // 0,4,8,12
    const size_t arow = (MODE == 0)
        ? ((size_t)((bb * 64 + r) * NHc + jb)) * Dc
        : ((size_t)(bb * 64 + r)) * Dc;
    const size_t brow = (MODE == 0)
        ? ((size_t)(2 * Dc + jb * 64 + r)) * Dc   // Wv rows of in_proj_w
        : ((size_t)(jb * 64 + r)) * Dc;
    const float* Ap = A + arow + c4;
    const float* Bp = Bw + brow + c4;

    for (int k0 = 0; k0 < Dc; k0 += 16) {
        const float4 va = *(const float4*)(Ap + k0);
        const float4 vb = *(const float4*)(Bp + k0);
        As[c4 + 0][r] = va.x; As[c4 + 1][r] = va.y;
        As[c4 + 2][r] = va.z; As[c4 + 3][r] = va.w;
        Bs[c4 + 0][r] = vb.x; Bs[c4 + 1][r] = vb.y;
        Bs[c4 + 2][r] = vb.z; Bs[c4 + 3][r] = vb.w;
        __syncthreads();
#pragma unroll
        for (int kk = 0; kk < 16; ++kk) {
            const float4 a4 = *(const float4*)(&As[kk][ty << 2]);
            const float4 b4 = *(const float4*)(&Bs[kk][tx << 2]);
            const float av[4] = {a4.x, a4.y, a4.z, a4.w};
            const float bv[4] = {b4.x, b4.y, b4.z, b4.w};
#pragma unroll
            for (int ii = 0; ii < 4; ++ii)
#pragma unroll
                for (int jj = 0; jj < 4; ++jj)
                    acc[ii][jj] = fmaf(av[ii], bv[jj], acc[ii][jj]);
        }
        __syncthreads();
    }

#pragma unroll
    for (int ii = 0; ii < 4; ++ii) {
        const int row = bb * 64 + (ty << 2) + ii;
#pragma unroll
        for (int jj = 0; jj < 4; ++jj) {
            const int col = jb * 64 + (tx << 2) + jj;
            float v = acc[ii][jj];
            if (MODE == 0) {
                g_CTX[(size_t)row * Dc + col] = v;
            } else if (MODE == 1) {
                const size_t o = (size_t)row * Dc + col;
                g_Z[o] = v + g_Z[o] + g_cbias[col];
            } else if (MODE == 2) {
                v += bias[col];
                v = 0.5f * v * (1.0f + erff(v * 0.70710678118654752f));
                g_T[(size_t)row * Dc + col] = v;
            } else {
                v += bias[col];
                if (v != v) v = 0.f;  // nan_to_num
                v = fminf(fmaxf(v, -3.402823466e38f), 3.402823466e38f);
                outp[(size_t)row * DOUTc + col] = v;
            }
        }
    }
}

// ---------------- row LayerNorm over g_Z -> g_Zn ---------------------------
__global__ __launch_bounds__(128) void k_ln(const float* __restrict__ gamma,
                                            const float* __restrict__ beta) {
    __shared__ float rs[4], rss[4];
    __shared__ float s_mu, s_inv;
    const int b = blockIdx.x, t = threadIdx.x;
    const int lane = t & 31, wid = t >> 5;
    const float* z = g_Z + (size_t)b * Dc;
    float x[4];
#pragma unroll
    for (int i = 0; i < 4; ++i) x[i] = z[t + (i << 7)];
    float s = x[0] + x[1] + x[2] + x[3];
    float ss = x[0] * x[0] + x[1] * x[1] + x[2] * x[2] + x[3] * x[3];
    s = warp_sum(s);
    ss = warp_sum(ss);
    if (lane == 0) { rs[wid] = s; rss[wid] = ss; }
    __syncthreads();
    if (t == 0) {
        const float S = rs[0] + rs[1] + rs[2] + rs[3];
        const float SS = rss[0] + rss[1] + rss[2] + rss[3];
        const float mu = S * (1.0f / Dc);
        const float var = SS * (1.0f / Dc) - mu * mu;
        s_mu = mu;
        s_inv = rsqrtf(var + 1e-5f);
    }
    __syncthreads();
    const float mu = s_mu, inv = s_inv;
    float* zn = g_Zn + (size_t)b * Dc;
#pragma unroll
    for (int i = 0; i < 4; ++i) {
        const int d = t + (i << 7);
        zn[d] = (x[i] - mu) * inv * gamma[d] + beta[d];
    }
}

// ---------------- launch ---------------------------------------------------
extern "C" void kernel_launch(void* const* d_in, const int* in_sizes, int n_in,
                              void* d_out, int out_size) {
    const float* H   = (const float*)d_in[0];
    const float* w   = (const float*)d_in[1];
    const float* agg = (const float*)d_in[2];
    const float* ipw = (const float*)d_in[3];
    const float* ipb = (const float*)d_in[4];
    const float* opw = (const float*)d_in[5];
    const float* opb = (const float*)d_in[6];
    const float* lng = (const float*)d_in[7];
    const float* lnb = (const float*)d_in[8];
    const float* w1  = (const float*)d_in[9];
    const float* b1  = (const float*)d_in[10];
    const float* w2  = (const float*)d_in[11];
    const float* b2  = (const float*)d_in[12];
    float* outp = (float*)d_out;

    const int Bn = in_sizes[0] / (Mc * Dc);   // 4096

    k_setup1<<<2 * Dc, 128>>>(agg, ipw, ipb, opw, opb);
    k_setup2<<<(NHc * Dc) / 256, 256>>>(ipw);
    k_attn<<<Bn, 256>>>(H, w);
    k_gemm<0><<<dim3(Bn / 64, NHc), 256>>>(ipw, nullptr, nullptr);
    k_gemm<1><<<dim3(Bn / 64, Dc / 64), 256>>>(opw, nullptr, nullptr);
    k_ln<<<Bn, 128>>>(lng, lnb);
    k_gemm<2><<<dim3(Bn / 64, Dc / 64), 256>>>(w1, b1, nullptr);
    k_gemm<3><<<dim3(Bn / 64, DOUTc / 64), 256>>>(w2, b2, outp);
}